// round 15
// baseline (speedup 1.0000x reference)
#include <cuda_runtime.h>
#include <cuda_fp16.h>
#include <math.h>
#include <stdint.h>

#define BB 2
#define LL 1024
#define DD 1024
#define EE 2048
#define NST 16
#define DTR 64
#define NLAYER 4
#define ML (BB*LL)          // 2048
#define XDBW (DTR + 2*NST)  // 96
#define SPLITK 8

#define SZ_IPW (NLAYER*2*EE*DD)
#define SZ_XPW (NLAYER*XDBW*EE)
#define SZ_DTW (NLAYER*EE*DTR)
#define SZ_OPW (NLAYER*DD*EE)

// ---------------- scratch (device globals; no allocation) ----------------
__device__ __align__(16) float g_resid[ML*DD];
__device__ __align__(16) float g_xz[ML*2*EE];
__device__ __align__(16) float g_xdb[ML*XDBW];
__device__ __align__(16) float g_xdb_part[SPLITK*ML*XDBW];
__device__ __align__(16) float g_h[ML*DD];

__device__ __align__(16) __half wb_ipw[SZ_IPW];
__device__ __align__(16) __half wb_xpw[SZ_XPW];
__device__ __align__(16) __half wb_dtw[SZ_DTW];
__device__ __align__(16) __half wb_opw[SZ_OPW];

__device__ __align__(16) __half a_hn16[ML*DD];
__device__ __align__(16) __half a_u16[ML*EE];
__device__ __align__(16) __half a_dtin16[ML*DTR];
__device__ __align__(16) __half a_dt16[ML*EE];
__device__ __align__(16) __half a_y16[ML*EE];

// ---------------- helpers ----------------
__device__ __forceinline__ uint32_t smem_to_u32(const void* p) {
    uint32_t a;
    asm("{ .reg .u64 t; cvta.to.shared.u64 t, %1; cvt.u32.u64 %0, t; }" : "=r"(a) : "l"(p));
    return a;
}
__device__ __forceinline__ void cp16(uint32_t s, const void* g) {
    asm volatile("cp.async.cg.shared.global [%0], [%1], 16;" :: "r"(s), "l"(g) : "memory");
}
__device__ __forceinline__ void cp16z(uint32_t s, const void* g, int srcsize) {
    asm volatile("cp.async.cg.shared.global [%0], [%1], 16, %2;"
                 :: "r"(s), "l"(g), "r"(srcsize) : "memory");
}
__device__ __forceinline__ void cp_commit() {
    asm volatile("cp.async.commit_group;" ::: "memory");
}
template <int N>
__device__ __forceinline__ void cp_wait() {
    asm volatile("cp.async.wait_group %0;" :: "n"(N) : "memory");
}
__device__ __forceinline__ void ldm_x4(uint32_t* r, uint32_t addr) {
    asm volatile("ldmatrix.sync.aligned.m8n8.x4.shared.b16 {%0,%1,%2,%3}, [%4];"
                 : "=r"(r[0]), "=r"(r[1]), "=r"(r[2]), "=r"(r[3]) : "r"(addr));
}
__device__ __forceinline__ void mma_f16(float* d, const uint32_t* a, uint32_t b0, uint32_t b1) {
    asm volatile(
        "mma.sync.aligned.m16n8k16.row.col.f32.f16.f16.f32 "
        "{%0,%1,%2,%3}, {%4,%5,%6,%7}, {%8,%9}, {%0,%1,%2,%3};"
        : "+f"(d[0]), "+f"(d[1]), "+f"(d[2]), "+f"(d[3])
        : "r"(a[0]), "r"(a[1]), "r"(a[2]), "r"(a[3]), "r"(b0), "r"(b1));
}

// ---------------- HMMA GEMM ----------------
// MODE 0: fp32 store. MODE 1: softplus(acc+bias) -> __half store (C is __half*).
#define NSTG 3

template <int KCH> struct GP {
    static constexpr int ROWB   = (KCH == 128) ? 272 : 144;
    static constexpr int TILE_B = 128 * ROWB;
    static constexpr int STAGE_B = 2 * TILE_B;
    static constexpr int GSMEM  = NSTG * STAGE_B;
    static constexpr int SEGS   = KCH / 8;
    static constexpr int NSTEP  = KCH / 16;
    static constexpr int LOAD_ITERS = (2 * 128 * SEGS) / 256;
};

template <int MODE, int KCH>
__global__ void __launch_bounds__(256, 1)
hmma_gemm(const __half* __restrict__ A16, const __half* __restrict__ B16,
          void* __restrict__ Cv, int N, int Kloop, int lda, int ldb,
          size_t czstride, const float* __restrict__ bias)
{
    using P = GP<KCH>;
    extern __shared__ char smem[];
    const uint32_t sb = smem_to_u32(smem);
    const int tid  = threadIdx.x;
    const int wid  = tid >> 5;
    const int lane = tid & 31;
    const int wm = wid >> 2;
    const int wn = wid & 3;
    const int row0 = blockIdx.y * 128;
    const int col0 = blockIdx.x * 128;
    const int kbase = blockIdx.z * Kloop;

    const int nc = Kloop / KCH;

    auto stage_of = [&](int c) { int m = c % NSTG; return (uint32_t)m * P::STAGE_B; };

    auto load_chunk = [&](int c) {
        if (c < nc) {
            const uint32_t base = sb + stage_of(c);
            const int k0 = kbase + c * KCH;
            #pragma unroll
            for (int it = 0; it < P::LOAD_ITERS; it++) {
                int s = tid + it * 256;
                int tile = s / (128 * P::SEGS);
                int rr = s % (128 * P::SEGS);
                int r = rr / P::SEGS;
                int seg = rr % P::SEGS;
                uint32_t off = base + (uint32_t)tile * P::TILE_B + (uint32_t)(r * P::ROWB + seg * 16);
                if (tile == 0) {
                    const __half* g = A16 + ((size_t)(row0 + r) * lda + k0 + seg * 8);
                    cp16(off, g);
                } else {
                    const __half* g = B16 + ((size_t)(col0 + r) * ldb + k0 + seg * 8);
                    cp16z(off, g, (col0 + r < N) ? 16 : 0);
                }
            }
        }
        cp_commit();
    };

    float acc[4][4][4];
    #pragma unroll
    for (int i = 0; i < 4; i++)
        #pragma unroll
        for (int j = 0; j < 4; j++)
            #pragma unroll
            for (int k = 0; k < 4; k++) acc[i][j][k] = 0.f;

    load_chunk(0);
    load_chunk(1);

    for (int c = 0; c < nc; c++) {
        cp_wait<NSTG - 2>();
        __syncthreads();

        const uint32_t base = sb + stage_of(c);

        #pragma unroll
        for (int s = 0; s < P::NSTEP; s++) {
            uint32_t af[4][4];
            uint32_t bf[2][4];

            #pragma unroll
            for (int mi = 0; mi < 4; mi++) {
                uint32_t addr = base
                    + (uint32_t)((wm * 64 + mi * 16 + (lane & 15)) * P::ROWB
                                 + s * 32 + (lane >> 4) * 16);
                ldm_x4(af[mi], addr);
            }
            #pragma unroll
            for (int nb = 0; nb < 2; nb++) {
                uint32_t addr = base + (uint32_t)P::TILE_B
                    + (uint32_t)((wn * 32 + nb * 16 + ((lane >> 4) & 1) * 8 + (lane & 7)) * P::ROWB
                                 + ((lane >> 3) & 1) * 16 + s * 32);
                ldm_x4(bf[nb], addr);
            }

            if (s == 0) load_chunk(c + 2);

            #pragma unroll
            for (int mi = 0; mi < 4; mi++) {
                #pragma unroll
                for (int n = 0; n < 4; n++) {
                    int nb = n >> 1, o = (n & 1) * 2;
                    mma_f16(acc[mi][n], af[mi], bf[nb][o], bf[nb][o + 1]);
                }
            }
        }
    }

    #pragma unroll
    for (int mi = 0; mi < 4; mi++) {
        #pragma unroll
        for (int n = 0; n < 4; n++) {
            int colb = col0 + wn * 32 + n * 8 + (lane & 3) * 2;
            #pragma unroll
            for (int half = 0; half < 2; half++) {
                int row = row0 + wm * 64 + mi * 16 + (lane >> 2) + half * 8;
                if (colb < N) {
                    float v0 = acc[mi][n][half * 2 + 0];
                    float v1 = acc[mi][n][half * 2 + 1];
                    if (MODE == 1) {
                        v0 += bias[colb];
                        v1 += bias[colb + 1];
                        v0 = (v0 > 20.f) ? v0 : log1pf(__expf(v0));
                        v1 = (v1 > 20.f) ? v1 : log1pf(__expf(v1));
                        __half* Cz = (__half*)Cv + (size_t)blockIdx.z * czstride;
                        *(__half2*)&Cz[(size_t)row * N + colb] = __floats2half2_rn(v0, v1);
                    } else {
                        float* Cz = (float*)Cv + (size_t)blockIdx.z * czstride;
                        *(float2*)&Cz[(size_t)row * N + colb] = make_float2(v0, v1);
                    }
                }
            }
        }
    }
}

#define GSMEM128 (GP<128>::GSMEM)
#define GSMEM64  (GP<64>::GSMEM)

// ---------------- merged weight convert (fp32 -> fp16) ----------------
#define N4_IPW (SZ_IPW/4)
#define N4_OPW (SZ_OPW/4)
#define N4_XPW (SZ_XPW/4)
#define N4_DTW (SZ_DTW/4)
#define N4_ALL (N4_IPW+N4_OPW+N4_XPW+N4_DTW)

__global__ void wconv_all_kernel(const float4* __restrict__ ipw,
                                 const float4* __restrict__ opw,
                                 const float4* __restrict__ xpw,
                                 const float4* __restrict__ dtw,
                                 __half2* __restrict__ ipw16,
                                 __half2* __restrict__ opw16,
                                 __half2* __restrict__ xpw16,
                                 __half2* __restrict__ dtw16)
{
    int i = blockIdx.x * 256 + threadIdx.x;
    if (i >= N4_ALL) return;
    const float4* src;
    __half2* dst;
    int j = i;
    if (j < N4_IPW)                 { src = ipw; dst = ipw16; }
    else if ((j -= N4_IPW) < N4_OPW){ src = opw; dst = opw16; }
    else if ((j -= N4_OPW) < N4_XPW){ src = xpw; dst = xpw16; }
    else { j -= N4_XPW;               src = dtw; dst = dtw16; }

    float4 v = src[j];
    dst[j * 2 + 0] = __floats2half2_rn(v.x, v.y);
    dst[j * 2 + 1] = __floats2half2_rn(v.z, v.w);
}

// ---------------- split-K reduce for xdb + fused dt_in extract (fp16) ----------------
__global__ void xdb_reduce_kernel(const float* __restrict__ part,
                                  float* __restrict__ xdb,
                                  __half* __restrict__ dtin16)
{
    int i = blockIdx.x * 256 + threadIdx.x;
    if (i >= ML * XDBW) return;
    float s = 0.f;
    #pragma unroll
    for (int z = 0; z < SPLITK; z++) s += part[(size_t)z * ML * XDBW + i];
    xdb[i] = s;
    int col = i % XDBW;
    if (col < DTR) {
        int row = i / XDBW;
        dtin16[row * DTR + col] = __float2half(s);
    }
}

// ---------------- fused (optional add) + RMSNorm; float4 vectorized ----------------
__global__ void addnorm_kernel(const float* __restrict__ a,
                               const float* __restrict__ badd,
                               const float* __restrict__ w,
                               float* __restrict__ resid_out,
                               float* __restrict__ f32_out,
                               __half* __restrict__ h16_out)
{
    int row = blockIdx.x;
    const float4* pa = (const float4*)(a + (size_t)row * DD) + threadIdx.x;
    const float4* pb = badd ? (const float4*)(badd + (size_t)row * DD) + threadIdx.x : nullptr;

    float4 v = *pa;
    if (pb) {
        float4 bv = *pb;
        v.x += bv.x; v.y += bv.y; v.z += bv.z; v.w += bv.w;
    }
    float ss = v.x * v.x + v.y * v.y + v.z * v.z + v.w * v.w;

    #pragma unroll
    for (int o = 16; o > 0; o >>= 1) ss += __shfl_xor_sync(0xffffffffu, ss, o);
    __shared__ float red[8];
    int wd = threadIdx.x >> 5;
    if ((threadIdx.x & 31) == 0) red[wd] = ss;
    __syncthreads();
    if (threadIdx.x < 32) {
        float vv = (threadIdx.x < 8) ? red[threadIdx.x] : 0.f;
        #pragma unroll
        for (int o = 4; o > 0; o >>= 1) vv += __shfl_xor_sync(0xffffffffu, vv, o);
        if (threadIdx.x == 0) red[0] = vv;
    }
    __syncthreads();
    float scale = rsqrtf(red[0] * (1.0f / DD) + 1e-5f);

    float4 wv = *((const float4*)w + threadIdx.x);
    float h0 = v.x * scale * wv.x;
    float h1 = v.y * scale * wv.y;
    float h2 = v.z * scale * wv.z;
    float h3 = v.w * scale * wv.w;

    size_t idx4 = (size_t)row * (DD / 4) + threadIdx.x;
    if (resid_out) ((float4*)resid_out)[idx4] = v;
    if (f32_out) ((float4*)f32_out)[idx4] = make_float4(h0, h1, h2, h3);
    if (h16_out) {
        __half2* o2 = (__half2*)h16_out + idx4 * 2;
        o2[0] = __floats2half2_rn(h0, h1);
        o2[1] = __floats2half2_rn(h2, h3);
    }
}

// ---------------- causal depthwise conv (k=4) + SiLU -> u16 only ----------------
__global__ void conv_silu_kernel(const float* __restrict__ xz,
                                 const float* __restrict__ cw,
                                 const float* __restrict__ cb,
                                 __half* __restrict__ u16)
{
    int idx = blockIdx.x * 256 + threadIdx.x;      // ML*EE/4 threads
    if (idx >= ML * EE / 4) return;
    int e = idx & (EE - 1);
    int g = idx >> 11;
    int l0 = (g & 255) * 4;
    int b = g >> 8;

    const size_t rowstride = 2 * EE;
    const float* x = xz + ((size_t)(b * LL + l0)) * rowstride + e;

    float xm3 = 0.f, xm2 = 0.f, xm1 = 0.f;
    if (l0 > 0) {
        xm1 = x[-1 * (ptrdiff_t)rowstride];
        xm2 = x[-2 * (ptrdiff_t)rowstride];
        xm3 = x[-3 * (ptrdiff_t)rowstride];
    }
    float x0 = x[0];
    float x1 = x[1 * rowstride];
    float x2 = x[2 * rowstride];
    float x3 = x[3 * rowstride];

    float w0 = cw[e * 4 + 0], w1 = cw[e * 4 + 1], w2 = cw[e * 4 + 2], w3 = cw[e * 4 + 3];
    float bias = cb[e];

    float v[4];
    v[0] = bias + w0 * xm3 + w1 * xm2 + w2 * xm1 + w3 * x0;
    v[1] = bias + w0 * xm2 + w1 * xm1 + w2 * x0  + w3 * x1;
    v[2] = bias + w0 * xm1 + w1 * x0  + w2 * x1  + w3 * x2;
    v[3] = bias + w0 * x0  + w1 * x1  + w2 * x2  + w3 * x3;

    size_t oidx = ((size_t)(b * LL + l0)) * EE + e;
    #pragma unroll
    for (int j = 0; j < 4; j++) {
        float a = v[j];
        float uv = a / (1.f + __expf(-a));
        u16[oidx + j * EE] = __float2half(uv);
    }
}

// ---------------- selective scan: fp16 dt/u inputs, 8 threads/channel ----------------
__global__ void __launch_bounds__(256) scan_kernel(
    const __half* __restrict__ dt16,
    const __half* __restrict__ u16,
    const float* __restrict__ xz,
    const float* __restrict__ xdb,
    const float* __restrict__ A_log,
    const float* __restrict__ Dp,
    __half* __restrict__ y16)
{
    int t = blockIdx.x * 256 + threadIdx.x;
    int n2 = t & 7;
    int c = t >> 3;
    int b = c >> 11;
    int e = c & (EE - 1);

    const float A0 = -__expf(A_log[e * NST + n2 * 2 + 0]);
    const float A1 = -__expf(A_log[e * NST + n2 * 2 + 1]);
    const float Dval = Dp[e];
    float h0 = 0.f, h1 = 0.f;

    const __half* pdt = dt16 + e;
    const __half* pu  = u16 + e;
    const float* pz  = xz + EE + e;
    const float2* pB = (const float2*)(xdb + DTR) + n2;
    const float2* pC = (const float2*)(xdb + DTR + NST) + n2;
    const size_t bl0 = (size_t)b * LL;
    const int XDBW2 = XDBW / 2;

    float fdt[4], fu[4], fz[4];
    float2 fB[4], fC[4];
    #pragma unroll
    for (int j = 0; j < 4; j++) {
        size_t bl = bl0 + j;
        fdt[j] = __half2float(__ldg(pdt + bl * EE));
        fu[j]  = __half2float(__ldg(pu + bl * EE));
        fz[j]  = __ldg(pz + bl * 2 * EE);
        fB[j]  = __ldg(pB + bl * XDBW2);
        fC[j]  = __ldg(pC + bl * XDBW2);
    }

    for (int l0 = 0; l0 < LL; l0 += 4) {
        float cdt[4], cu[4], cz[4];
        float2 cB[4], cC[4];
        #pragma unroll
        for (int j = 0; j < 4; j++) {
            cdt[j] = fdt[j]; cu[j] = fu[j]; cz[j] = fz[j]; cB[j] = fB[j]; cC[j] = fC[j];
        }
        if (l0 + 4 < LL) {
            #pragma unroll
            for (int j = 0; j < 4; j++) {
                size_t bl = bl0 + l0 + 4 + j;
                fdt[j] = __half2float(__ldg(pdt + bl * EE));
                fu[j]  = __half2float(__ldg(pu + bl * EE));
                fz[j]  = __ldg(pz + bl * 2 * EE);
                fB[j]  = __ldg(pB + bl * XDBW2);
                fC[j]  = __ldg(pC + bl * XDBW2);
            }
        }
        #pragma unroll
        for (int j = 0; j < 4; j++) {
            float dtv = cdt[j], uv = cu[j], zv = cz[j];
            float dtu = dtv * uv;
            float dA0 = __expf(dtv * A0);
            float dA1 = __expf(dtv * A1);
            h0 = fmaf(dA0, h0, dtu * cB[j].x);
            h1 = fmaf(dA1, h1, dtu * cB[j].y);
            float p = fmaf(h0, cC[j].x, h1 * cC[j].y);
            p += __shfl_xor_sync(0xffffffffu, p, 1);
            p += __shfl_xor_sync(0xffffffffu, p, 2);
            p += __shfl_xor_sync(0xffffffffu, p, 4);
            if (n2 == 0) {
                float sig = 1.f / (1.f + __expf(-zv));
                float out = (p + uv * Dval) * (zv * sig);
                y16[(bl0 + l0 + j) * EE + e] = __float2half(out);
            }
        }
    }
}

// ---------------- launch ----------------
extern "C" void kernel_launch(void* const* d_in, const int* in_sizes, int n_in,
                              void* d_out, int out_size)
{
    (void)in_sizes; (void)n_in; (void)out_size;
    const float* hidden = (const float*)d_in[0];
    const float* ipw    = (const float*)d_in[1];
    const float* cw     = (const float*)d_in[2];
    const float* cb     = (const float*)d_in[3];
    const float* xpw    = (const float*)d_in[4];
    const float* dtw    = (const float*)d_in[5];
    const float* dtb    = (const float*)d_in[6];
    const float* A_log  = (const float*)d_in[7];
    const float* Dp     = (const float*)d_in[8];
    const float* opw    = (const float*)d_in[9];
    const float* nw     = (const float*)d_in[10];
    const float* nfw    = (const float*)d_in[11];

    float *p_resid, *p_xz, *p_xdb, *p_xdbp, *p_h;
    cudaGetSymbolAddress((void**)&p_resid, g_resid);
    cudaGetSymbolAddress((void**)&p_xz,    g_xz);
    cudaGetSymbolAddress((void**)&p_xdb,   g_xdb);
    cudaGetSymbolAddress((void**)&p_xdbp,  g_xdb_part);
    cudaGetSymbolAddress((void**)&p_h,     g_h);

    __half *ipw16, *xpw16, *dtw16, *opw16;
    __half *hn16, *u16, *dtin16, *dt16, *y16;
    cudaGetSymbolAddress((void**)&ipw16, wb_ipw);
    cudaGetSymbolAddress((void**)&xpw16, wb_xpw);
    cudaGetSymbolAddress((void**)&dtw16, wb_dtw);
    cudaGetSymbolAddress((void**)&opw16, wb_opw);
    cudaGetSymbolAddress((void**)&hn16,   a_hn16);
    cudaGetSymbolAddress((void**)&u16,    a_u16);
    cudaGetSymbolAddress((void**)&dtin16, a_dtin16);
    cudaGetSymbolAddress((void**)&dt16,   a_dt16);
    cudaGetSymbolAddress((void**)&y16,    a_y16);

    cudaFuncSetAttribute((const void*)hmma_gemm<0,128>, cudaFuncAttributeMaxDynamicSharedMemorySize, GSMEM128);
    cudaFuncSetAttribute((const void*)hmma_gemm<1,64>,  cudaFuncAttributeMaxDynamicSharedMemorySize, GSMEM64);

    wconv_all_kernel<<<(N4_ALL + 255) / 256, 256>>>(
        (const float4*)ipw, (const float4*)opw, (const float4*)xpw, (const float4*)dtw,
        (__half2*)ipw16, (__half2*)opw16, (__half2*)xpw16, (__half2*)dtw16);

    for (int i = 0; i < NLAYER; i++) {
        const float* cw_i  = cw  + (size_t)i * EE * 4;
        const float* cb_i  = cb  + (size_t)i * EE;
        const float* dtb_i = dtb + (size_t)i * EE;
        const float* Al_i  = A_log + (size_t)i * EE * NST;
        const float* Dp_i  = Dp  + (size_t)i * EE;
        const float* nw_i  = nw  + (size_t)i * DD;

        if (i == 0)
            addnorm_kernel<<<ML, 256>>>(hidden, nullptr, nw_i, p_resid, nullptr, hn16);
        else
            addnorm_kernel<<<ML, 256>>>(p_resid, p_h, nw_i, p_resid, nullptr, hn16);

        // xz = hn @ ipw^T   (2048 x 4096 x 1024)
        hmma_gemm<0,128><<<dim3(32, 16, 1), 256, GSMEM128>>>(
            hn16, ipw16 + (size_t)i * 2 * EE * DD,
            p_xz, 4096, DD, DD, DD, 0, nullptr);

        // u = silu(conv(xi) + cb) -> fp16
        conv_silu_kernel<<<(ML * EE / 4) / 256, 256>>>(p_xz, cw_i, cb_i, u16);

        // xdb partials = u @ xpw^T, split-K x8
        hmma_gemm<0,128><<<dim3(1, 16, SPLITK), 256, GSMEM128>>>(
            u16, xpw16 + (size_t)i * XDBW * EE,
            p_xdbp, XDBW, EE / SPLITK, EE, EE, (size_t)ML * XDBW, nullptr);

        // reduce partials -> xdb; extract dt_in (fp16)
        xdb_reduce_kernel<<<(ML * XDBW + 255) / 256, 256>>>(p_xdbp, p_xdb, dtin16);

        // dt = softplus(dt_in @ dtw^T + dtb) -> fp16
        hmma_gemm<1,64><<<dim3(16, 16, 1), 256, GSMEM64>>>(
            dtin16, dtw16 + (size_t)i * EE * DTR,
            dt16, EE, DTR, DTR, DTR, 0, dtb_i);

        // selective scan + skip + gate -> y (fp16)
        scan_kernel<<<(BB * EE * 8) / 256, 256>>>(dt16, u16, p_xz, p_xdb, Al_i, Dp_i, y16);

        // h = y @ opw^T   (2048 x 1024 x 2048)
        hmma_gemm<0,128><<<dim3(8, 16, 1), 256, GSMEM128>>>(
            y16, opw16 + (size_t)i * DD * EE,
            p_h, DD, EE, EE, EE, 0, nullptr);
    }

    addnorm_kernel<<<ML, 256>>>(p_h, p_resid, nfw, nullptr, (float*)d_out, nullptr);
}

// round 16
// speedup vs baseline: 1.2296x; 1.2296x over previous
#include <cuda_runtime.h>
#include <cuda_fp16.h>
#include <math.h>
#include <stdint.h>

#define BB 2
#define LL 1024
#define DD 1024
#define EE 2048
#define NST 16
#define DTR 64
#define NLAYER 4
#define ML (BB*LL)          // 2048
#define XDBW (DTR + 2*NST)  // 96
#define SPLITK 8

#define SZ_IPW (NLAYER*2*EE*DD)
#define SZ_XPW (NLAYER*XDBW*EE)
#define SZ_DTW (NLAYER*EE*DTR)
#define SZ_OPW (NLAYER*DD*EE)

// ---------------- scratch (device globals; no allocation) ----------------
__device__ __align__(16) float g_resid[ML*DD];
__device__ __align__(16) float g_xz[ML*2*EE];
__device__ __align__(16) float g_u[ML*EE];
__device__ __align__(16) float g_xdb[ML*XDBW];
__device__ __align__(16) float g_xdb_part[SPLITK*ML*XDBW];
__device__ __align__(16) float g_dt[ML*EE];
__device__ __align__(16) float g_h[ML*DD];

__device__ __align__(16) __half wb_ipw[SZ_IPW];
__device__ __align__(16) __half wb_xpw[SZ_XPW];
__device__ __align__(16) __half wb_dtw[SZ_DTW];
__device__ __align__(16) __half wb_opw[SZ_OPW];

__device__ __align__(16) __half a_hn16[ML*DD];
__device__ __align__(16) __half a_u16[ML*EE];
__device__ __align__(16) __half a_dt16[ML*DTR];
__device__ __align__(16) __half a_y16[ML*EE];

// ---------------- helpers ----------------
__device__ __forceinline__ uint32_t smem_to_u32(const void* p) {
    uint32_t a;
    asm("{ .reg .u64 t; cvta.to.shared.u64 t, %1; cvt.u32.u64 %0, t; }" : "=r"(a) : "l"(p));
    return a;
}
__device__ __forceinline__ void cp16(uint32_t s, const void* g) {
    asm volatile("cp.async.cg.shared.global [%0], [%1], 16;" :: "r"(s), "l"(g) : "memory");
}
__device__ __forceinline__ void cp16z(uint32_t s, const void* g, int srcsize) {
    asm volatile("cp.async.cg.shared.global [%0], [%1], 16, %2;"
                 :: "r"(s), "l"(g), "r"(srcsize) : "memory");
}
__device__ __forceinline__ void cp_commit() {
    asm volatile("cp.async.commit_group;" ::: "memory");
}
template <int N>
__device__ __forceinline__ void cp_wait() {
    asm volatile("cp.async.wait_group %0;" :: "n"(N) : "memory");
}
__device__ __forceinline__ void ldm_x4(uint32_t* r, uint32_t addr) {
    asm volatile("ldmatrix.sync.aligned.m8n8.x4.shared.b16 {%0,%1,%2,%3}, [%4];"
                 : "=r"(r[0]), "=r"(r[1]), "=r"(r[2]), "=r"(r[3]) : "r"(addr));
}
__device__ __forceinline__ void mma_f16(float* d, const uint32_t* a, uint32_t b0, uint32_t b1) {
    asm volatile(
        "mma.sync.aligned.m16n8k16.row.col.f32.f16.f16.f32 "
        "{%0,%1,%2,%3}, {%4,%5,%6,%7}, {%8,%9}, {%0,%1,%2,%3};"
        : "+f"(d[0]), "+f"(d[1]), "+f"(d[2]), "+f"(d[3])
        : "r"(a[0]), "r"(a[1]), "r"(a[2]), "r"(a[3]), "r"(b0), "r"(b1));
}

// ---------------- HMMA GEMM: C[M,N] = A16[M,K]*B16[N,K]^T (pure fp16, f32 accum) ----------------
#define NSTG 3

template <int KCH> struct GP {
    static constexpr int ROWB   = (KCH == 128) ? 272 : 144;
    static constexpr int TILE_B = 128 * ROWB;
    static constexpr int STAGE_B = 2 * TILE_B;
    static constexpr int GSMEM  = NSTG * STAGE_B;
    static constexpr int SEGS   = KCH / 8;
    static constexpr int NSTEP  = KCH / 16;
    static constexpr int LOAD_ITERS = (2 * 128 * SEGS) / 256;
};

template <int MODE, int KCH>
__global__ void __launch_bounds__(256, 1)
hmma_gemm(const __half* __restrict__ A16, const __half* __restrict__ B16,
          float* __restrict__ C, int N, int Kloop, int lda, int ldb,
          size_t czstride, const float* __restrict__ bias)
{
    using P = GP<KCH>;
    extern __shared__ char smem[];
    const uint32_t sb = smem_to_u32(smem);
    const int tid  = threadIdx.x;
    const int wid  = tid >> 5;
    const int lane = tid & 31;
    const int wm = wid >> 2;
    const int wn = wid & 3;
    const int row0 = blockIdx.y * 128;
    const int col0 = blockIdx.x * 128;
    const int kbase = blockIdx.z * Kloop;

    const int nc = Kloop / KCH;

    auto stage_of = [&](int c) { int m = c % NSTG; return (uint32_t)m * P::STAGE_B; };

    auto load_chunk = [&](int c) {
        if (c < nc) {
            const uint32_t base = sb + stage_of(c);
            const int k0 = kbase + c * KCH;
            #pragma unroll
            for (int it = 0; it < P::LOAD_ITERS; it++) {
                int s = tid + it * 256;
                int tile = s / (128 * P::SEGS);
                int rr = s % (128 * P::SEGS);
                int r = rr / P::SEGS;
                int seg = rr % P::SEGS;
                uint32_t off = base + (uint32_t)tile * P::TILE_B + (uint32_t)(r * P::ROWB + seg * 16);
                if (tile == 0) {
                    const __half* g = A16 + ((size_t)(row0 + r) * lda + k0 + seg * 8);
                    cp16(off, g);
                } else {
                    const __half* g = B16 + ((size_t)(col0 + r) * ldb + k0 + seg * 8);
                    cp16z(off, g, (col0 + r < N) ? 16 : 0);
                }
            }
        }
        cp_commit();
    };

    float acc[4][4][4];
    #pragma unroll
    for (int i = 0; i < 4; i++)
        #pragma unroll
        for (int j = 0; j < 4; j++)
            #pragma unroll
            for (int k = 0; k < 4; k++) acc[i][j][k] = 0.f;

    load_chunk(0);
    load_chunk(1);

    for (int c = 0; c < nc; c++) {
        cp_wait<NSTG - 2>();
        __syncthreads();

        const uint32_t base = sb + stage_of(c);

        #pragma unroll
        for (int s = 0; s < P::NSTEP; s++) {
            uint32_t af[4][4];
            uint32_t bf[2][4];

            #pragma unroll
            for (int mi = 0; mi < 4; mi++) {
                uint32_t addr = base
                    + (uint32_t)((wm * 64 + mi * 16 + (lane & 15)) * P::ROWB
                                 + s * 32 + (lane >> 4) * 16);
                ldm_x4(af[mi], addr);
            }
            #pragma unroll
            for (int nb = 0; nb < 2; nb++) {
                uint32_t addr = base + (uint32_t)P::TILE_B
                    + (uint32_t)((wn * 32 + nb * 16 + ((lane >> 4) & 1) * 8 + (lane & 7)) * P::ROWB
                                 + ((lane >> 3) & 1) * 16 + s * 32);
                ldm_x4(bf[nb], addr);
            }

            if (s == 0) load_chunk(c + 2);

            #pragma unroll
            for (int mi = 0; mi < 4; mi++) {
                #pragma unroll
                for (int n = 0; n < 4; n++) {
                    int nb = n >> 1, o = (n & 1) * 2;
                    mma_f16(acc[mi][n], af[mi], bf[nb][o], bf[nb][o + 1]);
                }
            }
        }
    }

    float* Cz = C + (size_t)blockIdx.z * czstride;
    #pragma unroll
    for (int mi = 0; mi < 4; mi++) {
        #pragma unroll
        for (int n = 0; n < 4; n++) {
            int colb = col0 + wn * 32 + n * 8 + (lane & 3) * 2;
            #pragma unroll
            for (int half = 0; half < 2; half++) {
                int row = row0 + wm * 64 + mi * 16 + (lane >> 2) + half * 8;
                if (colb < N) {
                    float v0 = acc[mi][n][half * 2 + 0];
                    float v1 = acc[mi][n][half * 2 + 1];
                    if (MODE == 1) {
                        v0 += bias[colb];
                        v1 += bias[colb + 1];
                        v0 = (v0 > 20.f) ? v0 : log1pf(__expf(v0));
                        v1 = (v1 > 20.f) ? v1 : log1pf(__expf(v1));
                    }
                    *(float2*)&Cz[(size_t)row * N + colb] = make_float2(v0, v1);
                }
            }
        }
    }
}

#define GSMEM128 (GP<128>::GSMEM)
#define GSMEM64  (GP<64>::GSMEM)

// ---------------- merged weight convert (fp32 -> fp16) ----------------
#define N4_IPW (SZ_IPW/4)
#define N4_OPW (SZ_OPW/4)
#define N4_XPW (SZ_XPW/4)
#define N4_DTW (SZ_DTW/4)
#define N4_ALL (N4_IPW+N4_OPW+N4_XPW+N4_DTW)

__global__ void wconv_all_kernel(const float4* __restrict__ ipw,
                                 const float4* __restrict__ opw,
                                 const float4* __restrict__ xpw,
                                 const float4* __restrict__ dtw,
                                 __half2* __restrict__ ipw16,
                                 __half2* __restrict__ opw16,
                                 __half2* __restrict__ xpw16,
                                 __half2* __restrict__ dtw16)
{
    int i = blockIdx.x * 256 + threadIdx.x;
    if (i >= N4_ALL) return;
    const float4* src;
    __half2* dst;
    int j = i;
    if (j < N4_IPW)                 { src = ipw; dst = ipw16; }
    else if ((j -= N4_IPW) < N4_OPW){ src = opw; dst = opw16; }
    else if ((j -= N4_OPW) < N4_XPW){ src = xpw; dst = xpw16; }
    else { j -= N4_XPW;               src = dtw; dst = dtw16; }

    float4 v = src[j];
    dst[j * 2 + 0] = __floats2half2_rn(v.x, v.y);
    dst[j * 2 + 1] = __floats2half2_rn(v.z, v.w);
}

// ---------------- split-K reduce for xdb + fused dt_in extract (fp16) ----------------
__global__ void xdb_reduce_kernel(const float* __restrict__ part,
                                  float* __restrict__ xdb,
                                  __half* __restrict__ dt16)
{
    int i = blockIdx.x * 256 + threadIdx.x;
    if (i >= ML * XDBW) return;
    float s = 0.f;
    #pragma unroll
    for (int z = 0; z < SPLITK; z++) s += part[(size_t)z * ML * XDBW + i];
    xdb[i] = s;
    int col = i % XDBW;
    if (col < DTR) {
        int row = i / XDBW;
        dt16[row * DTR + col] = __float2half(s);
    }
}

// ---------------- fused (optional add) + RMSNorm; float4 vectorized ----------------
__global__ void addnorm_kernel(const float* __restrict__ a,
                               const float* __restrict__ badd,
                               const float* __restrict__ w,
                               float* __restrict__ resid_out,
                               float* __restrict__ f32_out,
                               __half* __restrict__ h16_out)
{
    int row = blockIdx.x;
    const float4* pa = (const float4*)(a + (size_t)row * DD) + threadIdx.x;
    const float4* pb = badd ? (const float4*)(badd + (size_t)row * DD) + threadIdx.x : nullptr;

    float4 v = *pa;
    if (pb) {
        float4 bv = *pb;
        v.x += bv.x; v.y += bv.y; v.z += bv.z; v.w += bv.w;
    }
    float ss = v.x * v.x + v.y * v.y + v.z * v.z + v.w * v.w;

    #pragma unroll
    for (int o = 16; o > 0; o >>= 1) ss += __shfl_xor_sync(0xffffffffu, ss, o);
    __shared__ float red[8];
    int wd = threadIdx.x >> 5;
    if ((threadIdx.x & 31) == 0) red[wd] = ss;
    __syncthreads();
    if (threadIdx.x < 32) {
        float vv = (threadIdx.x < 8) ? red[threadIdx.x] : 0.f;
        #pragma unroll
        for (int o = 4; o > 0; o >>= 1) vv += __shfl_xor_sync(0xffffffffu, vv, o);
        if (threadIdx.x == 0) red[0] = vv;
    }
    __syncthreads();
    float scale = rsqrtf(red[0] * (1.0f / DD) + 1e-5f);

    float4 wv = *((const float4*)w + threadIdx.x);
    float h0 = v.x * scale * wv.x;
    float h1 = v.y * scale * wv.y;
    float h2 = v.z * scale * wv.z;
    float h3 = v.w * scale * wv.w;

    size_t idx4 = (size_t)row * (DD / 4) + threadIdx.x;
    if (resid_out) ((float4*)resid_out)[idx4] = v;
    if (f32_out) ((float4*)f32_out)[idx4] = make_float4(h0, h1, h2, h3);
    if (h16_out) {
        __half2* o2 = (__half2*)h16_out + idx4 * 2;
        o2[0] = __floats2half2_rn(h0, h1);
        o2[1] = __floats2half2_rn(h2, h3);
    }
}

// ---------------- causal depthwise conv (k=4) + SiLU; 4 timesteps per thread ----------------
__global__ void conv_silu_kernel(const float* __restrict__ xz,
                                 const float* __restrict__ cw,
                                 const float* __restrict__ cb,
                                 float* __restrict__ u,
                                 __half* __restrict__ u16)
{
    int idx = blockIdx.x * 256 + threadIdx.x;      // ML*EE/4 threads
    if (idx >= ML * EE / 4) return;
    int e = idx & (EE - 1);
    int g = idx >> 11;
    int l0 = (g & 255) * 4;
    int b = g >> 8;

    const size_t rowstride = 2 * EE;
    const float* x = xz + ((size_t)(b * LL + l0)) * rowstride + e;

    float xm3 = 0.f, xm2 = 0.f, xm1 = 0.f;
    if (l0 > 0) {
        xm1 = x[-1 * (ptrdiff_t)rowstride];
        xm2 = x[-2 * (ptrdiff_t)rowstride];
        xm3 = x[-3 * (ptrdiff_t)rowstride];
    }
    float x0 = x[0];
    float x1 = x[1 * rowstride];
    float x2 = x[2 * rowstride];
    float x3 = x[3 * rowstride];

    float w0 = cw[e * 4 + 0], w1 = cw[e * 4 + 1], w2 = cw[e * 4 + 2], w3 = cw[e * 4 + 3];
    float bias = cb[e];

    float v[4];
    v[0] = bias + w0 * xm3 + w1 * xm2 + w2 * xm1 + w3 * x0;
    v[1] = bias + w0 * xm2 + w1 * xm1 + w2 * x0  + w3 * x1;
    v[2] = bias + w0 * xm1 + w1 * x0  + w2 * x1  + w3 * x2;
    v[3] = bias + w0 * x0  + w1 * x1  + w2 * x2  + w3 * x3;

    size_t oidx = ((size_t)(b * LL + l0)) * EE + e;
    #pragma unroll
    for (int j = 0; j < 4; j++) {
        float a = v[j];
        float uv = a / (1.f + __expf(-a));
        u[oidx + j * EE] = uv;
        u16[oidx + j * EE] = __float2half(uv);
    }
}

// ---------------- selective scan: 8 threads/channel, 2 states/thread, prefetch 4 ----------------
__global__ void __launch_bounds__(256) scan_kernel(
    const float* __restrict__ dt,
    const float* __restrict__ ub,
    const float* __restrict__ xz,
    const float* __restrict__ xdb,
    const float* __restrict__ A_log,
    const float* __restrict__ Dp,
    __half* __restrict__ y16)
{
    int t = blockIdx.x * 256 + threadIdx.x;
    int n2 = t & 7;
    int c = t >> 3;
    int b = c >> 11;
    int e = c & (EE - 1);

    const float A0 = -__expf(A_log[e * NST + n2 * 2 + 0]);
    const float A1 = -__expf(A_log[e * NST + n2 * 2 + 1]);
    const float Dval = Dp[e];
    float h0 = 0.f, h1 = 0.f;

    const float* pdt = dt + e;
    const float* pu  = ub + e;
    const float* pz  = xz + EE + e;
    const float2* pB = (const float2*)(xdb + DTR) + n2;
    const float2* pC = (const float2*)(xdb + DTR + NST) + n2;
    const size_t bl0 = (size_t)b * LL;
    const int XDBW2 = XDBW / 2;

    float fdt[4], fu[4], fz[4];
    float2 fB[4], fC[4];
    #pragma unroll
    for (int j = 0; j < 4; j++) {
        size_t bl = bl0 + j;
        fdt[j] = __ldg(pdt + bl * EE);
        fu[j]  = __ldg(pu + bl * EE);
        fz[j]  = __ldg(pz + bl * 2 * EE);
        fB[j]  = __ldg(pB + bl * XDBW2);
        fC[j]  = __ldg(pC + bl * XDBW2);
    }

    for (int l0 = 0; l0 < LL; l0 += 4) {
        float cdt[4], cu[4], cz[4];
        float2 cB[4], cC[4];
        #pragma unroll
        for (int j = 0; j < 4; j++) {
            cdt[j] = fdt[j]; cu[j] = fu[j]; cz[j] = fz[j]; cB[j] = fB[j]; cC[j] = fC[j];
        }
        if (l0 + 4 < LL) {
            #pragma unroll
            for (int j = 0; j < 4; j++) {
                size_t bl = bl0 + l0 + 4 + j;
                fdt[j] = __ldg(pdt + bl * EE);
                fu[j]  = __ldg(pu + bl * EE);
                fz[j]  = __ldg(pz + bl * 2 * EE);
                fB[j]  = __ldg(pB + bl * XDBW2);
                fC[j]  = __ldg(pC + bl * XDBW2);
            }
        }
        #pragma unroll
        for (int j = 0; j < 4; j++) {
            float dtv = cdt[j], uv = cu[j], zv = cz[j];
            float dtu = dtv * uv;
            float dA0 = __expf(dtv * A0);
            float dA1 = __expf(dtv * A1);
            h0 = fmaf(dA0, h0, dtu * cB[j].x);
            h1 = fmaf(dA1, h1, dtu * cB[j].y);
            float p = fmaf(h0, cC[j].x, h1 * cC[j].y);
            p += __shfl_xor_sync(0xffffffffu, p, 1);
            p += __shfl_xor_sync(0xffffffffu, p, 2);
            p += __shfl_xor_sync(0xffffffffu, p, 4);
            if (n2 == 0) {
                float sig = 1.f / (1.f + __expf(-zv));
                float out = (p + uv * Dval) * (zv * sig);
                y16[(bl0 + l0 + j) * EE + e] = __float2half(out);
            }
        }
    }
}

// ---------------- launch ----------------
extern "C" void kernel_launch(void* const* d_in, const int* in_sizes, int n_in,
                              void* d_out, int out_size)
{
    (void)in_sizes; (void)n_in; (void)out_size;
    const float* hidden = (const float*)d_in[0];
    const float* ipw    = (const float*)d_in[1];
    const float* cw     = (const float*)d_in[2];
    const float* cb     = (const float*)d_in[3];
    const float* xpw    = (const float*)d_in[4];
    const float* dtw    = (const float*)d_in[5];
    const float* dtb    = (const float*)d_in[6];
    const float* A_log  = (const float*)d_in[7];
    const float* Dp     = (const float*)d_in[8];
    const float* opw    = (const float*)d_in[9];
    const float* nw     = (const float*)d_in[10];
    const float* nfw    = (const float*)d_in[11];

    float *p_resid, *p_xz, *p_u, *p_xdb, *p_xdbp, *p_dt, *p_h;
    cudaGetSymbolAddress((void**)&p_resid, g_resid);
    cudaGetSymbolAddress((void**)&p_xz,    g_xz);
    cudaGetSymbolAddress((void**)&p_u,     g_u);
    cudaGetSymbolAddress((void**)&p_xdb,   g_xdb);
    cudaGetSymbolAddress((void**)&p_xdbp,  g_xdb_part);
    cudaGetSymbolAddress((void**)&p_dt,    g_dt);
    cudaGetSymbolAddress((void**)&p_h,     g_h);

    __half *ipw16, *xpw16, *dtw16, *opw16;
    __half *hn16, *u16, *dt16, *y16;
    cudaGetSymbolAddress((void**)&ipw16, wb_ipw);
    cudaGetSymbolAddress((void**)&xpw16, wb_xpw);
    cudaGetSymbolAddress((void**)&dtw16, wb_dtw);
    cudaGetSymbolAddress((void**)&opw16, wb_opw);
    cudaGetSymbolAddress((void**)&hn16, a_hn16);
    cudaGetSymbolAddress((void**)&u16,  a_u16);
    cudaGetSymbolAddress((void**)&dt16, a_dt16);
    cudaGetSymbolAddress((void**)&y16,  a_y16);

    cudaFuncSetAttribute((const void*)hmma_gemm<0,128>, cudaFuncAttributeMaxDynamicSharedMemorySize, GSMEM128);
    cudaFuncSetAttribute((const void*)hmma_gemm<1,64>,  cudaFuncAttributeMaxDynamicSharedMemorySize, GSMEM64);

    wconv_all_kernel<<<(N4_ALL + 255) / 256, 256>>>(
        (const float4*)ipw, (const float4*)opw, (const float4*)xpw, (const float4*)dtw,
        (__half2*)ipw16, (__half2*)opw16, (__half2*)xpw16, (__half2*)dtw16);

    for (int i = 0; i < NLAYER; i++) {
        const float* cw_i  = cw  + (size_t)i * EE * 4;
        const float* cb_i  = cb  + (size_t)i * EE;
        const float* dtb_i = dtb + (size_t)i * EE;
        const float* Al_i  = A_log + (size_t)i * EE * NST;
        const float* Dp_i  = Dp  + (size_t)i * EE;
        const float* nw_i  = nw  + (size_t)i * DD;

        if (i == 0)
            addnorm_kernel<<<ML, 256>>>(hidden, nullptr, nw_i, p_resid, nullptr, hn16);
        else
            addnorm_kernel<<<ML, 256>>>(p_resid, p_h, nw_i, p_resid, nullptr, hn16);

        // xz = hn @ ipw^T   (2048 x 4096 x 1024)
        hmma_gemm<0,128><<<dim3(32, 16, 1), 256, GSMEM128>>>(
            hn16, ipw16 + (size_t)i * 2 * EE * DD,
            p_xz, 4096, DD, DD, DD, 0, nullptr);

        // u = silu(conv(xi) + cb)
        conv_silu_kernel<<<(ML * EE / 4) / 256, 256>>>(p_xz, cw_i, cb_i, p_u, u16);

        // xdb partials = u @ xpw^T, split-K x8
        hmma_gemm<0,128><<<dim3(1, 16, SPLITK), 256, GSMEM128>>>(
            u16, xpw16 + (size_t)i * XDBW * EE,
            p_xdbp, XDBW, EE / SPLITK, EE, EE, (size_t)ML * XDBW, nullptr);

        // reduce partials -> xdb; extract dt_in (fp16)
        xdb_reduce_kernel<<<(ML * XDBW + 255) / 256, 256>>>(p_xdbp, p_xdb, dt16);

        // dt = softplus(dt_in @ dtw^T + dtb)   (2048 x 2048 x 64) — K=64 chunk
        hmma_gemm<1,64><<<dim3(16, 16, 1), 256, GSMEM64>>>(
            dt16, dtw16 + (size_t)i * EE * DTR,
            p_dt, EE, DTR, DTR, DTR, 0, dtb_i);

        // selective scan + skip + gate -> y (fp16)
        scan_kernel<<<(BB * EE * 8) / 256, 256>>>(p_dt, p_u, p_xz, p_xdb, Al_i, Dp_i, y16);

        // h = y @ opw^T   (2048 x 1024 x 2048)
        hmma_gemm<0,128><<<dim3(8, 16, 1), 256, GSMEM128>>>(
            y16, opw16 + (size_t)i * DD * EE,
            p_h, DD, EE, EE, EE, 0, nullptr);
    }

    addnorm_kernel<<<ML, 256>>>(p_h, p_resid, nfw, nullptr, (float*)d_out, nullptr);
}

// round 17
// speedup vs baseline: 1.2477x; 1.0148x over previous
#include <cuda_runtime.h>
#include <cuda_fp16.h>
#include <math.h>
#include <stdint.h>

#define BB 2
#define LL 1024
#define DD 1024
#define EE 2048
#define NST 16
#define DTR 64
#define NLAYER 4
#define ML (BB*LL)          // 2048
#define XDBW (DTR + 2*NST)  // 96
#define SPLITK 8

#define SZ_IPW (NLAYER*2*EE*DD)
#define SZ_XPW (NLAYER*XDBW*EE)
#define SZ_DTW (NLAYER*EE*DTR)
#define SZ_OPW (NLAYER*DD*EE)

// ---------------- scratch (device globals; no allocation) ----------------
__device__ __align__(16) float g_resid[ML*DD];
__device__ __align__(16) float g_xz[ML*2*EE];
__device__ __align__(16) float g_u[ML*EE];
__device__ __align__(16) float g_xdb[ML*XDBW];
__device__ __align__(16) float g_xdb_part[SPLITK*ML*XDBW];
__device__ __align__(16) float g_dt[ML*EE];
__device__ __align__(16) float g_h[ML*DD];

__device__ __align__(16) __half wb_ipw[SZ_IPW];
__device__ __align__(16) __half wb_xpw[SZ_XPW];
__device__ __align__(16) __half wb_dtw[SZ_DTW];
__device__ __align__(16) __half wb_opw[SZ_OPW];

__device__ __align__(16) __half a_hn16[ML*DD];
__device__ __align__(16) __half a_u16[ML*EE];
__device__ __align__(16) __half a_dt16[ML*DTR];
__device__ __align__(16) __half a_y16[ML*EE];

// ---------------- helpers ----------------
__device__ __forceinline__ uint32_t smem_to_u32(const void* p) {
    uint32_t a;
    asm("{ .reg .u64 t; cvta.to.shared.u64 t, %1; cvt.u32.u64 %0, t; }" : "=r"(a) : "l"(p));
    return a;
}
__device__ __forceinline__ void cp16(uint32_t s, const void* g) {
    asm volatile("cp.async.cg.shared.global [%0], [%1], 16;" :: "r"(s), "l"(g) : "memory");
}
__device__ __forceinline__ void cp16z(uint32_t s, const void* g, int srcsize) {
    asm volatile("cp.async.cg.shared.global [%0], [%1], 16, %2;"
                 :: "r"(s), "l"(g), "r"(srcsize) : "memory");
}
__device__ __forceinline__ void cp_commit() {
    asm volatile("cp.async.commit_group;" ::: "memory");
}
template <int N>
__device__ __forceinline__ void cp_wait() {
    asm volatile("cp.async.wait_group %0;" :: "n"(N) : "memory");
}
__device__ __forceinline__ void ldm_x4(uint32_t* r, uint32_t addr) {
    asm volatile("ldmatrix.sync.aligned.m8n8.x4.shared.b16 {%0,%1,%2,%3}, [%4];"
                 : "=r"(r[0]), "=r"(r[1]), "=r"(r[2]), "=r"(r[3]) : "r"(addr));
}
__device__ __forceinline__ void mma_f16(float* d, const uint32_t* a, uint32_t b0, uint32_t b1) {
    asm volatile(
        "mma.sync.aligned.m16n8k16.row.col.f32.f16.f16.f32 "
        "{%0,%1,%2,%3}, {%4,%5,%6,%7}, {%8,%9}, {%0,%1,%2,%3};"
        : "+f"(d[0]), "+f"(d[1]), "+f"(d[2]), "+f"(d[3])
        : "r"(a[0]), "r"(a[1]), "r"(a[2]), "r"(a[3]), "r"(b0), "r"(b1));
}

// ---------------- HMMA GEMM: C[M,N] = A16[M,K]*B16[N,K]^T (pure fp16, f32 accum) ----------------
#define NSTG 3

template <int KCH> struct GP {
    static constexpr int ROWB   = (KCH == 128) ? 272 : 144;
    static constexpr int TILE_B = 128 * ROWB;
    static constexpr int STAGE_B = 2 * TILE_B;
    static constexpr int GSMEM  = NSTG * STAGE_B;
    static constexpr int SEGS   = KCH / 8;
    static constexpr int NSTEP  = KCH / 16;
    static constexpr int LOAD_ITERS = (2 * 128 * SEGS) / 256;
};

template <int MODE, int KCH>
__global__ void __launch_bounds__(256, 1)
hmma_gemm(const __half* __restrict__ A16, const __half* __restrict__ B16,
          float* __restrict__ C, int N, int Kloop, int lda, int ldb,
          size_t czstride, const float* __restrict__ bias)
{
    using P = GP<KCH>;
    extern __shared__ char smem[];
    const uint32_t sb = smem_to_u32(smem);
    const int tid  = threadIdx.x;
    const int wid  = tid >> 5;
    const int lane = tid & 31;
    const int wm = wid >> 2;
    const int wn = wid & 3;
    const int row0 = blockIdx.y * 128;
    const int col0 = blockIdx.x * 128;
    const int kbase = blockIdx.z * Kloop;

    const int nc = Kloop / KCH;

    auto stage_of = [&](int c) { int m = c % NSTG; return (uint32_t)m * P::STAGE_B; };

    auto load_chunk = [&](int c) {
        if (c < nc) {
            const uint32_t base = sb + stage_of(c);
            const int k0 = kbase + c * KCH;
            #pragma unroll
            for (int it = 0; it < P::LOAD_ITERS; it++) {
                int s = tid + it * 256;
                int tile = s / (128 * P::SEGS);
                int rr = s % (128 * P::SEGS);
                int r = rr / P::SEGS;
                int seg = rr % P::SEGS;
                uint32_t off = base + (uint32_t)tile * P::TILE_B + (uint32_t)(r * P::ROWB + seg * 16);
                if (tile == 0) {
                    const __half* g = A16 + ((size_t)(row0 + r) * lda + k0 + seg * 8);
                    cp16(off, g);
                } else {
                    const __half* g = B16 + ((size_t)(col0 + r) * ldb + k0 + seg * 8);
                    cp16z(off, g, (col0 + r < N) ? 16 : 0);
                }
            }
        }
        cp_commit();
    };

    float acc[4][4][4];
    #pragma unroll
    for (int i = 0; i < 4; i++)
        #pragma unroll
        for (int j = 0; j < 4; j++)
            #pragma unroll
            for (int k = 0; k < 4; k++) acc[i][j][k] = 0.f;

    load_chunk(0);
    load_chunk(1);

    for (int c = 0; c < nc; c++) {
        cp_wait<NSTG - 2>();
        __syncthreads();

        const uint32_t base = sb + stage_of(c);

        #pragma unroll
        for (int s = 0; s < P::NSTEP; s++) {
            uint32_t af[4][4];
            uint32_t bf[2][4];

            #pragma unroll
            for (int mi = 0; mi < 4; mi++) {
                uint32_t addr = base
                    + (uint32_t)((wm * 64 + mi * 16 + (lane & 15)) * P::ROWB
                                 + s * 32 + (lane >> 4) * 16);
                ldm_x4(af[mi], addr);
            }
            #pragma unroll
            for (int nb = 0; nb < 2; nb++) {
                uint32_t addr = base + (uint32_t)P::TILE_B
                    + (uint32_t)((wn * 32 + nb * 16 + ((lane >> 4) & 1) * 8 + (lane & 7)) * P::ROWB
                                 + ((lane >> 3) & 1) * 16 + s * 32);
                ldm_x4(bf[nb], addr);
            }

            if (s == 0) load_chunk(c + 2);

            #pragma unroll
            for (int mi = 0; mi < 4; mi++) {
                #pragma unroll
                for (int n = 0; n < 4; n++) {
                    int nb = n >> 1, o = (n & 1) * 2;
                    mma_f16(acc[mi][n], af[mi], bf[nb][o], bf[nb][o + 1]);
                }
            }
        }
    }

    float* Cz = C + (size_t)blockIdx.z * czstride;
    #pragma unroll
    for (int mi = 0; mi < 4; mi++) {
        #pragma unroll
        for (int n = 0; n < 4; n++) {
            int colb = col0 + wn * 32 + n * 8 + (lane & 3) * 2;
            #pragma unroll
            for (int half = 0; half < 2; half++) {
                int row = row0 + wm * 64 + mi * 16 + (lane >> 2) + half * 8;
                if (colb < N) {
                    float v0 = acc[mi][n][half * 2 + 0];
                    float v1 = acc[mi][n][half * 2 + 1];
                    if (MODE == 1) {
                        v0 += bias[colb];
                        v1 += bias[colb + 1];
                        v0 = (v0 > 20.f) ? v0 : log1pf(__expf(v0));
                        v1 = (v1 > 20.f) ? v1 : log1pf(__expf(v1));
                    }
                    *(float2*)&Cz[(size_t)row * N + colb] = make_float2(v0, v1);
                }
            }
        }
    }
}

#define GSMEM128 (GP<128>::GSMEM)
#define GSMEM64  (GP<64>::GSMEM)

// ---------------- merged weight convert (fp32 -> fp16) ----------------
#define N4_IPW (SZ_IPW/4)
#define N4_OPW (SZ_OPW/4)
#define N4_XPW (SZ_XPW/4)
#define N4_DTW (SZ_DTW/4)
#define N4_ALL (N4_IPW+N4_OPW+N4_XPW+N4_DTW)

__global__ void wconv_all_kernel(const float4* __restrict__ ipw,
                                 const float4* __restrict__ opw,
                                 const float4* __restrict__ xpw,
                                 const float4* __restrict__ dtw,
                                 __half2* __restrict__ ipw16,
                                 __half2* __restrict__ opw16,
                                 __half2* __restrict__ xpw16,
                                 __half2* __restrict__ dtw16)
{
    int i = blockIdx.x * 256 + threadIdx.x;
    if (i >= N4_ALL) return;
    const float4* src;
    __half2* dst;
    int j = i;
    if (j < N4_IPW)                 { src = ipw; dst = ipw16; }
    else if ((j -= N4_IPW) < N4_OPW){ src = opw; dst = opw16; }
    else if ((j -= N4_OPW) < N4_XPW){ src = xpw; dst = xpw16; }
    else { j -= N4_XPW;               src = dtw; dst = dtw16; }

    float4 v = src[j];
    dst[j * 2 + 0] = __floats2half2_rn(v.x, v.y);
    dst[j * 2 + 1] = __floats2half2_rn(v.z, v.w);
}

// ---------------- split-K reduce for xdb + fused dt_in extract (fp16) ----------------
__global__ void xdb_reduce_kernel(const float* __restrict__ part,
                                  float* __restrict__ xdb,
                                  __half* __restrict__ dt16)
{
    int i = blockIdx.x * 256 + threadIdx.x;
    if (i >= ML * XDBW) return;
    float s = 0.f;
    #pragma unroll
    for (int z = 0; z < SPLITK; z++) s += part[(size_t)z * ML * XDBW + i];
    xdb[i] = s;
    int col = i % XDBW;
    if (col < DTR) {
        int row = i / XDBW;
        dt16[row * DTR + col] = __float2half(s);
    }
}

// ---------------- fused (optional add) + RMSNorm; float4 vectorized ----------------
__global__ void addnorm_kernel(const float* __restrict__ a,
                               const float* __restrict__ badd,
                               const float* __restrict__ w,
                               float* __restrict__ resid_out,
                               float* __restrict__ f32_out,
                               __half* __restrict__ h16_out)
{
    int row = blockIdx.x;
    const float4* pa = (const float4*)(a + (size_t)row * DD) + threadIdx.x;
    const float4* pb = badd ? (const float4*)(badd + (size_t)row * DD) + threadIdx.x : nullptr;

    float4 v = *pa;
    if (pb) {
        float4 bv = *pb;
        v.x += bv.x; v.y += bv.y; v.z += bv.z; v.w += bv.w;
    }
    float ss = v.x * v.x + v.y * v.y + v.z * v.z + v.w * v.w;

    #pragma unroll
    for (int o = 16; o > 0; o >>= 1) ss += __shfl_xor_sync(0xffffffffu, ss, o);
    __shared__ float red[8];
    int wd = threadIdx.x >> 5;
    if ((threadIdx.x & 31) == 0) red[wd] = ss;
    __syncthreads();
    if (threadIdx.x < 32) {
        float vv = (threadIdx.x < 8) ? red[threadIdx.x] : 0.f;
        #pragma unroll
        for (int o = 4; o > 0; o >>= 1) vv += __shfl_xor_sync(0xffffffffu, vv, o);
        if (threadIdx.x == 0) red[0] = vv;
    }
    __syncthreads();
    float scale = rsqrtf(red[0] * (1.0f / DD) + 1e-5f);

    float4 wv = *((const float4*)w + threadIdx.x);
    float h0 = v.x * scale * wv.x;
    float h1 = v.y * scale * wv.y;
    float h2 = v.z * scale * wv.z;
    float h3 = v.w * scale * wv.w;

    size_t idx4 = (size_t)row * (DD / 4) + threadIdx.x;
    if (resid_out) ((float4*)resid_out)[idx4] = v;
    if (f32_out) ((float4*)f32_out)[idx4] = make_float4(h0, h1, h2, h3);
    if (h16_out) {
        __half2* o2 = (__half2*)h16_out + idx4 * 2;
        o2[0] = __floats2half2_rn(h0, h1);
        o2[1] = __floats2half2_rn(h2, h3);
    }
}

// ---------------- causal depthwise conv (k=4) + SiLU; 4 timesteps per thread ----------------
__global__ void conv_silu_kernel(const float* __restrict__ xz,
                                 const float* __restrict__ cw,
                                 const float* __restrict__ cb,
                                 float* __restrict__ u,
                                 __half* __restrict__ u16)
{
    int idx = blockIdx.x * 256 + threadIdx.x;      // ML*EE/4 threads
    if (idx >= ML * EE / 4) return;
    int e = idx & (EE - 1);
    int g = idx >> 11;
    int l0 = (g & 255) * 4;
    int b = g >> 8;

    const size_t rowstride = 2 * EE;
    const float* x = xz + ((size_t)(b * LL + l0)) * rowstride + e;

    float xm3 = 0.f, xm2 = 0.f, xm1 = 0.f;
    if (l0 > 0) {
        xm1 = x[-1 * (ptrdiff_t)rowstride];
        xm2 = x[-2 * (ptrdiff_t)rowstride];
        xm3 = x[-3 * (ptrdiff_t)rowstride];
    }
    float x0 = x[0];
    float x1 = x[1 * rowstride];
    float x2 = x[2 * rowstride];
    float x3 = x[3 * rowstride];

    float w0 = cw[e * 4 + 0], w1 = cw[e * 4 + 1], w2 = cw[e * 4 + 2], w3 = cw[e * 4 + 3];
    float bias = cb[e];

    float v[4];
    v[0] = bias + w0 * xm3 + w1 * xm2 + w2 * xm1 + w3 * x0;
    v[1] = bias + w0 * xm2 + w1 * xm1 + w2 * x0  + w3 * x1;
    v[2] = bias + w0 * xm1 + w1 * x0  + w2 * x1  + w3 * x2;
    v[3] = bias + w0 * x0  + w1 * x1  + w2 * x2  + w3 * x3;

    size_t oidx = ((size_t)(b * LL + l0)) * EE + e;
    #pragma unroll
    for (int j = 0; j < 4; j++) {
        float a = v[j];
        float uv = a / (1.f + __expf(-a));
        u[oidx + j * EE] = uv;
        u16[oidx + j * EE] = __float2half(uv);
    }
}

// ---------------- selective scan: 8 threads/channel, 2 states/thread, prefetch 4 ----------------
// 128-thread blocks (grid 256) for finer SM placement on the 148-SM chip.
__global__ void __launch_bounds__(128) scan_kernel(
    const float* __restrict__ dt,
    const float* __restrict__ ub,
    const float* __restrict__ xz,
    const float* __restrict__ xdb,
    const float* __restrict__ A_log,
    const float* __restrict__ Dp,
    __half* __restrict__ y16)
{
    int t = blockIdx.x * 128 + threadIdx.x;
    int n2 = t & 7;
    int c = t >> 3;
    int b = c >> 11;
    int e = c & (EE - 1);

    const float A0 = -__expf(A_log[e * NST + n2 * 2 + 0]);
    const float A1 = -__expf(A_log[e * NST + n2 * 2 + 1]);
    const float Dval = Dp[e];
    float h0 = 0.f, h1 = 0.f;

    const float* pdt = dt + e;
    const float* pu  = ub + e;
    const float* pz  = xz + EE + e;
    const float2* pB = (const float2*)(xdb + DTR) + n2;
    const float2* pC = (const float2*)(xdb + DTR + NST) + n2;
    const size_t bl0 = (size_t)b * LL;
    const int XDBW2 = XDBW / 2;

    float fdt[4], fu[4], fz[4];
    float2 fB[4], fC[4];
    #pragma unroll
    for (int j = 0; j < 4; j++) {
        size_t bl = bl0 + j;
        fdt[j] = __ldg(pdt + bl * EE);
        fu[j]  = __ldg(pu + bl * EE);
        fz[j]  = __ldg(pz + bl * 2 * EE);
        fB[j]  = __ldg(pB + bl * XDBW2);
        fC[j]  = __ldg(pC + bl * XDBW2);
    }

    for (int l0 = 0; l0 < LL; l0 += 4) {
        float cdt[4], cu[4], cz[4];
        float2 cB[4], cC[4];
        #pragma unroll
        for (int j = 0; j < 4; j++) {
            cdt[j] = fdt[j]; cu[j] = fu[j]; cz[j] = fz[j]; cB[j] = fB[j]; cC[j] = fC[j];
        }
        if (l0 + 4 < LL) {
            #pragma unroll
            for (int j = 0; j < 4; j++) {
                size_t bl = bl0 + l0 + 4 + j;
                fdt[j] = __ldg(pdt + bl * EE);
                fu[j]  = __ldg(pu + bl * EE);
                fz[j]  = __ldg(pz + bl * 2 * EE);
                fB[j]  = __ldg(pB + bl * XDBW2);
                fC[j]  = __ldg(pC + bl * XDBW2);
            }
        }
        #pragma unroll
        for (int j = 0; j < 4; j++) {
            float dtv = cdt[j], uv = cu[j], zv = cz[j];
            float dtu = dtv * uv;
            float dA0 = __expf(dtv * A0);
            float dA1 = __expf(dtv * A1);
            h0 = fmaf(dA0, h0, dtu * cB[j].x);
            h1 = fmaf(dA1, h1, dtu * cB[j].y);
            float p = fmaf(h0, cC[j].x, h1 * cC[j].y);
            p += __shfl_xor_sync(0xffffffffu, p, 1);
            p += __shfl_xor_sync(0xffffffffu, p, 2);
            p += __shfl_xor_sync(0xffffffffu, p, 4);
            if (n2 == 0) {
                float sig = 1.f / (1.f + __expf(-zv));
                float out = (p + uv * Dval) * (zv * sig);
                y16[(bl0 + l0 + j) * EE + e] = __float2half(out);
            }
        }
    }
}

// ---------------- launch ----------------
extern "C" void kernel_launch(void* const* d_in, const int* in_sizes, int n_in,
                              void* d_out, int out_size)
{
    (void)in_sizes; (void)n_in; (void)out_size;
    const float* hidden = (const float*)d_in[0];
    const float* ipw    = (const float*)d_in[1];
    const float* cw     = (const float*)d_in[2];
    const float* cb     = (const float*)d_in[3];
    const float* xpw    = (const float*)d_in[4];
    const float* dtw    = (const float*)d_in[5];
    const float* dtb    = (const float*)d_in[6];
    const float* A_log  = (const float*)d_in[7];
    const float* Dp     = (const float*)d_in[8];
    const float* opw    = (const float*)d_in[9];
    const float* nw     = (const float*)d_in[10];
    const float* nfw    = (const float*)d_in[11];

    float *p_resid, *p_xz, *p_u, *p_xdb, *p_xdbp, *p_dt, *p_h;
    cudaGetSymbolAddress((void**)&p_resid, g_resid);
    cudaGetSymbolAddress((void**)&p_xz,    g_xz);
    cudaGetSymbolAddress((void**)&p_u,     g_u);
    cudaGetSymbolAddress((void**)&p_xdb,   g_xdb);
    cudaGetSymbolAddress((void**)&p_xdbp,  g_xdb_part);
    cudaGetSymbolAddress((void**)&p_dt,    g_dt);
    cudaGetSymbolAddress((void**)&p_h,     g_h);

    __half *ipw16, *xpw16, *dtw16, *opw16;
    __half *hn16, *u16, *dt16, *y16;
    cudaGetSymbolAddress((void**)&ipw16, wb_ipw);
    cudaGetSymbolAddress((void**)&xpw16, wb_xpw);
    cudaGetSymbolAddress((void**)&dtw16, wb_dtw);
    cudaGetSymbolAddress((void**)&opw16, wb_opw);
    cudaGetSymbolAddress((void**)&hn16, a_hn16);
    cudaGetSymbolAddress((void**)&u16,  a_u16);
    cudaGetSymbolAddress((void**)&dt16, a_dt16);
    cudaGetSymbolAddress((void**)&y16,  a_y16);

    cudaFuncSetAttribute((const void*)hmma_gemm<0,128>, cudaFuncAttributeMaxDynamicSharedMemorySize, GSMEM128);
    cudaFuncSetAttribute((const void*)hmma_gemm<1,64>,  cudaFuncAttributeMaxDynamicSharedMemorySize, GSMEM64);

    wconv_all_kernel<<<(N4_ALL + 255) / 256, 256>>>(
        (const float4*)ipw, (const float4*)opw, (const float4*)xpw, (const float4*)dtw,
        (__half2*)ipw16, (__half2*)opw16, (__half2*)xpw16, (__half2*)dtw16);

    for (int i = 0; i < NLAYER; i++) {
        const float* cw_i  = cw  + (size_t)i * EE * 4;
        const float* cb_i  = cb  + (size_t)i * EE;
        const float* dtb_i = dtb + (size_t)i * EE;
        const float* Al_i  = A_log + (size_t)i * EE * NST;
        const float* Dp_i  = Dp  + (size_t)i * EE;
        const float* nw_i  = nw  + (size_t)i * DD;

        if (i == 0)
            addnorm_kernel<<<ML, 256>>>(hidden, nullptr, nw_i, p_resid, nullptr, hn16);
        else
            addnorm_kernel<<<ML, 256>>>(p_resid, p_h, nw_i, p_resid, nullptr, hn16);

        // xz = hn @ ipw^T   (2048 x 4096 x 1024)
        hmma_gemm<0,128><<<dim3(32, 16, 1), 256, GSMEM128>>>(
            hn16, ipw16 + (size_t)i * 2 * EE * DD,
            p_xz, 4096, DD, DD, DD, 0, nullptr);

        // u = silu(conv(xi) + cb)
        conv_silu_kernel<<<(ML * EE / 4) / 256, 256>>>(p_xz, cw_i, cb_i, p_u, u16);

        // xdb partials = u @ xpw^T, split-K x8
        hmma_gemm<0,128><<<dim3(1, 16, SPLITK), 256, GSMEM128>>>(
            u16, xpw16 + (size_t)i * XDBW * EE,
            p_xdbp, XDBW, EE / SPLITK, EE, EE, (size_t)ML * XDBW, nullptr);

        // reduce partials -> xdb; extract dt_in (fp16)
        xdb_reduce_kernel<<<(ML * XDBW + 255) / 256, 256>>>(p_xdbp, p_xdb, dt16);

        // dt = softplus(dt_in @ dtw^T + dtb)   (2048 x 2048 x 64)
        hmma_gemm<1,64><<<dim3(16, 16, 1), 256, GSMEM64>>>(
            dt16, dtw16 + (size_t)i * EE * DTR,
            p_dt, EE, DTR, DTR, DTR, 0, dtb_i);

        // selective scan + skip + gate -> y (fp16); 128-thread blocks
        scan_kernel<<<(BB * EE * 8) / 128, 128>>>(p_dt, p_u, p_xz, p_xdb, Al_i, Dp_i, y16);

        // h = y @ opw^T   (2048 x 1024 x 2048)
        hmma_gemm<0,128><<<dim3(8, 16, 1), 256, GSMEM128>>>(
            y16, opw16 + (size_t)i * DD * EE,
            p_h, DD, EE, EE, EE, 0, nullptr);
    }

    addnorm_kernel<<<ML, 256>>>(p_h, p_resid, nfw, nullptr, (float*)d_out, nullptr);
}